// round 4
// baseline (speedup 1.0000x reference)
#include <cuda_runtime.h>
#include <math.h>

#define NSAMP   480000
#define SRATE   48000.0f
#define MAXDEL  50
#define M_PER   25                 // elements per thread in scan kernels
#define PTH     (NSAMP / M_PER)    // 19200 scan threads total
#define BLK     256
#define K1_GRID (PTH / BLK)        // 75 blocks
#define K2_PER  (PTH / BLK)        // 75 partials per K2 thread
#define SEG     (BLK * M_PER)      // 6400 elements per K1/K3 block

// scratch (static device globals — no allocation)
__device__ float g_part_lo[PTH];
__device__ float g_part_hi[PTH];
__device__ float g_carry_lo[PTH];
__device__ float g_carry_hi[PTH];
__device__ float g_filt[NSAMP];

struct RParams {
    float a_lo, a_hi, fb, gain;
    int L, nd;
};

__device__ __forceinline__ RParams get_params(const float* __restrict__ p) {
    RParams r;
    float freq = fminf(fmaxf(p[0], 20.0f), SRATE * 0.5f);
    r.fb   = fminf(fmaxf(p[1], 0.0f), 0.99f);
    r.a_lo = fminf(fmaxf(p[2], 1e-7f), 0.99f);
    r.a_hi = fminf(fmaxf(p[3], 1e-7f), 0.99f);
    r.gain = fmaxf(p[4], 1e-7f);
    float dl = floorf(SRATE / freq);
    dl = fminf(fmaxf(dl, 1.0f), (float)(NSAMP / 2));
    r.L = (int)dl;
    int nd = NSAMP / r.L;
    r.nd = nd < MAXDEL ? nd : MAXDEL;
    return r;
}

// ---------------------------------------------------------------------------
// K1: per-thread local recurrence partials (zero init) for both lowpasses.
// ---------------------------------------------------------------------------
__global__ __launch_bounds__(BLK) void k1_partials(
    const float* __restrict__ buf, const float* __restrict__ p)
{
    __shared__ float s[SEG];
    const int base = blockIdx.x * SEG;
    for (int i = threadIdx.x; i < SEG; i += BLK) s[i] = buf[base + i];
    __syncthreads();

    RParams rp = get_params(p);
    const float a_lo = rp.a_lo, d_lo = 1.0f - rp.a_lo;
    const float a_hi = rp.a_hi, d_hi = 1.0f - rp.a_hi;

    float ylo = 0.0f, yhi = 0.0f;
    const int off = threadIdx.x * M_PER;
#pragma unroll
    for (int k = 0; k < M_PER; k++) {
        float x = s[off + k];
        ylo = fmaf(a_lo, x, d_lo * ylo);
        yhi = fmaf(a_hi, x, d_hi * yhi);
    }
    const int g = blockIdx.x * BLK + threadIdx.x;
    g_part_lo[g] = ylo;
    g_part_hi[g] = yhi;
}

// ---------------------------------------------------------------------------
// K2: single block. Affine scan over all 19200 thread partials -> exclusive
// carry (value of y entering each thread segment) for both recurrences.
// Each affine map is y -> v + D*y (D = per-segment decay, identical for all
// segments), applied earliest-first.
// ---------------------------------------------------------------------------
__global__ __launch_bounds__(BLK) void k2_carries(const float* __restrict__ p)
{
    __shared__ float sv_lo[BLK], sv_hi[BLK], sp_lo[BLK], sp_hi[BLK];

    RParams rp = get_params(p);
    const float d_lo = 1.0f - rp.a_lo;
    const float d_hi = 1.0f - rp.a_hi;

    // per-segment decay D = d^M_PER
    float D_lo = 1.0f, D_hi = 1.0f;
#pragma unroll
    for (int k = 0; k < M_PER; k++) { D_lo *= d_lo; D_hi *= d_hi; }

    const int t = threadIdx.x;

    // serially compose this thread's K2_PER consecutive segments
    float Vlo = 0.0f, Vhi = 0.0f;
    float Plo = 1.0f, Phi = 1.0f;
    const int gbase = t * K2_PER;
#pragma unroll 5
    for (int j = 0; j < K2_PER; j++) {
        Vlo = fmaf(D_lo, Vlo, g_part_lo[gbase + j]);
        Vhi = fmaf(D_hi, Vhi, g_part_hi[gbase + j]);
        Plo *= D_lo; Phi *= D_hi;
    }

    sv_lo[t] = Vlo; sv_hi[t] = Vhi;
    sp_lo[t] = Plo; sp_hi[t] = Phi;
    __syncthreads();

    // Hillis-Steele inclusive scan over 256 threads (affine composition)
    for (int s = 1; s < BLK; s <<= 1) {
        float lvlo = 0.0f, lvhi = 0.0f, lplo = 1.0f, lphi = 1.0f;
        if (t >= s) {
            lvlo = sv_lo[t - s]; lvhi = sv_hi[t - s];
            lplo = sp_lo[t - s]; lphi = sp_hi[t - s];
        }
        float vlo = sv_lo[t], vhi = sv_hi[t];
        float plo = sp_lo[t], phi = sp_hi[t];
        __syncthreads();
        sv_lo[t] = fmaf(plo, lvlo, vlo);
        sv_hi[t] = fmaf(phi, lvhi, vhi);
        sp_lo[t] = plo * lplo;
        sp_hi[t] = phi * lphi;
        __syncthreads();
    }

    // exclusive carry entering this thread's group (initial state is 0,
    // so carry = inclusive prefix value of the previous thread)
    float Clo = (t > 0) ? sv_lo[t - 1] : 0.0f;
    float Chi = (t > 0) ? sv_hi[t - 1] : 0.0f;

    // walk segments again writing per-segment exclusive carries
#pragma unroll 5
    for (int j = 0; j < K2_PER; j++) {
        const int g = gbase + j;
        g_carry_lo[g] = Clo;
        g_carry_hi[g] = Chi;
        Clo = fmaf(D_lo, Clo, g_part_lo[g]);
        Chi = fmaf(D_hi, Chi, g_part_hi[g]);
    }
}

// ---------------------------------------------------------------------------
// K3: replay recurrence with exact incoming carry, write filtered = y_hi - y_lo
// ---------------------------------------------------------------------------
__global__ __launch_bounds__(BLK) void k3_filter(
    const float* __restrict__ buf, const float* __restrict__ p)
{
    __shared__ float s[SEG];
    const int base = blockIdx.x * SEG;
    for (int i = threadIdx.x; i < SEG; i += BLK) s[i] = buf[base + i];
    __syncthreads();

    RParams rp = get_params(p);
    const float a_lo = rp.a_lo, d_lo = 1.0f - rp.a_lo;
    const float a_hi = rp.a_hi, d_hi = 1.0f - rp.a_hi;

    const int g = blockIdx.x * BLK + threadIdx.x;
    float ylo = g_carry_lo[g];
    float yhi = g_carry_hi[g];

    const int off = threadIdx.x * M_PER;
#pragma unroll
    for (int k = 0; k < M_PER; k++) {
        float x = s[off + k];
        ylo = fmaf(a_lo, x, d_lo * ylo);
        yhi = fmaf(a_hi, x, d_hi * yhi);
        s[off + k] = yhi - ylo;     // bandpass = hi_lp - lo_lp
    }
    __syncthreads();
    for (int i = threadIdx.x; i < SEG; i += BLK) g_filt[base + i] = s[i];
}

// ---------------------------------------------------------------------------
// K4: comb-sum of delayed, feedback-scaled filtered signal + tanh(gain * .)
// ---------------------------------------------------------------------------
__global__ __launch_bounds__(BLK) void k4_output(
    const float* __restrict__ in_sig, const float* __restrict__ p,
    float* __restrict__ out)
{
    const int n = blockIdx.x * BLK + threadIdx.x;
    if (n >= NSAMP) return;

    RParams rp = get_params(p);
    const int L = rp.L, nd = rp.nd;
    const float fb = rp.fb;

    float sum = in_sig[n];
    float fbp = 1.0f;
    int shift = 0;
#pragma unroll 8
    for (int i = 1; i < MAXDEL; i++) {
        shift += L;
        fbp *= fb;
        if (i >= nd || shift >= NSAMP) break;  // tap inactive (monotone in i)
        if (shift > n) break;                  // causality; shift monotone -> break
        sum = fmaf(fbp, __ldg(&g_filt[n - shift]), sum);
    }
    out[n] = tanhf(sum * rp.gain);
}

// ---------------------------------------------------------------------------
extern "C" void kernel_launch(void* const* d_in, const int* in_sizes, int n_in,
                              void* d_out, int out_size)
{
    const float* input_signal = (const float*)d_in[0];
    const float* parameters   = (const float*)d_in[1];
    const float* delay_buffer = (const float*)d_in[2];
    float* out = (float*)d_out;

    k1_partials<<<K1_GRID, BLK>>>(delay_buffer, parameters);
    k2_carries<<<1, BLK>>>(parameters);
    k3_filter<<<K1_GRID, BLK>>>(delay_buffer, parameters);
    k4_output<<<(NSAMP + BLK - 1) / BLK, BLK>>>(input_signal, parameters, out);
}